// round 17
// baseline (speedup 1.0000x reference)
#include <cuda_runtime.h>
#include <stdint.h>

#define BB 64
#define NN 68
#define ZZ 384
#define MM 46
#define DC 7
#define EE (MM*DC)   /* 322 */
#define NITER 10

#define CT 96        /* check threads per check: each owns 4 z (one u32) */
#define CM 2         /* checks per CTA */
#define WX 12        /* writer CTAs appended to check grid */
#define WZ 32        /* z rows per writer CTA (12*32 = 384) */

// prev / x2 rows are PERMUTED: edges of the same variable occupy contiguous
// rows. g_edge_row[e] maps a check-order edge to its row offset (x ZZ).
__device__ __align__(128) int8_t g_prev[BB * EE * ZZ];   // ~7.9 MB
__device__ __align__(128) int8_t g_x2[BB * EE * ZZ];     // ~7.9 MB
// t16[b][n][z] = 16 * (xa + msg_sum/16); out = t16/16
__device__ __align__(16)  float  g_t16[BB * NN * ZZ];    // ~6.7 MB
__device__ int g_var_deg[NN];
__device__ int g_var_start[NN];     // row start * ZZ
__device__ int g_edge_row[EE];      // permuted row * ZZ (check-order indexed)

// ---------------------------------------------------------------------------
// Setup: counting-sort edges by variable -> contiguous rows per variable.
// Slot order within a variable is atomic (nondeterministic) but the var sum
// is an exact integer add (commutative) -> output bit-identical.
// ---------------------------------------------------------------------------
__global__ void setup_csr(const int* __restrict__ etv) {
    __shared__ int cnt[NN], start[NN], slot[EE];
    const int t = threadIdx.x;
    if (t < NN) cnt[t] = 0;
    __syncthreads();
    if (t < EE) slot[t] = atomicAdd(&cnt[etv[t]], 1);
    __syncthreads();
    if (t == 0) {
        int acc = 0;
        for (int n = 0; n < NN; ++n) { start[n] = acc; acc += cnt[n]; }
    }
    __syncthreads();
    if (t < EE) g_edge_row[t] = (start[etv[t]] + slot[t]) * ZZ;
    if (t < NN) {
        g_var_deg[t]   = cnt[t];
        g_var_start[t] = start[t] * ZZ;
    }
}

// quantize value scaled by 16: code = sign(d) * min(rint(|d|), 31), as byte
__device__ __forceinline__ uint32_t qbyte(float d) {
    const float q = fminf(rintf(fabsf(d)), 31.0f);
    const int c = (int)(d < 0.0f ? -q : q);
    return (uint32_t)c & 0xFFu;
}

// ---------------------------------------------------------------------------
// Initial x2(0) = Q(xa) codes in permuted rows. Grid (E, B) x 96 threads.
// ---------------------------------------------------------------------------
__global__ void __launch_bounds__(CT)
init_x2(const float* __restrict__ xa, const int* __restrict__ etv) {
    const int e = blockIdx.x;
    const int b = blockIdx.y;
    const int t = threadIdx.x;
    const int v = etv[e];
    const float4 xv = *(const float4*)(xa + (size_t)(b * NN + v) * ZZ + 4 * t);
    const uint32_t w = qbyte(xv.x * 16.0f)
                     | (qbyte(xv.y * 16.0f) << 8)
                     | (qbyte(xv.z * 16.0f) << 16)
                     | (qbyte(xv.w * 16.0f) << 24);
    *(uint32_t*)(g_x2 + (size_t)(b * EE) * ZZ + g_edge_row[e] + 4 * t) = w;
}

// ---------------------------------------------------------------------------
// Out-writer work unit: out[b][z0..z0+31][:] = t16[b][:][z0..z0+31] / 16
// (192 threads; smem transpose; coalesced 272B-row streaming stores)
// ---------------------------------------------------------------------------
__device__ __forceinline__ void write_out_part(int wb, int b,
                                               float* __restrict__ out_slice,
                                               int tid) {
    __shared__ float tile[NN][WZ + 1];
    const int z0 = wb * WZ;
    const float* __restrict__ tp = g_t16 + (size_t)b * NN * ZZ + z0;

    for (int idx = tid; idx < NN * (WZ / 4); idx += CT * CM) {
        const int n  = idx >> 3;        // WZ/4 = 8
        const int zc = idx & 7;
        const float4 v = *(const float4*)(tp + (size_t)n * ZZ + 4 * zc);
        tile[n][4 * zc + 0] = v.x * 0.0625f;
        tile[n][4 * zc + 1] = v.y * 0.0625f;
        tile[n][4 * zc + 2] = v.z * 0.0625f;
        tile[n][4 * zc + 3] = v.w * 0.0625f;
    }
    __syncthreads();

    float* __restrict__ op = out_slice + (size_t)(b * ZZ + z0) * NN;
    for (int idx = tid; idx < WZ * (NN / 4); idx += CT * CM) {
        const int zl = idx / 17;
        const int nq = idx - zl * 17;
        float4 v;
        v.x = tile[4 * nq + 0][zl];
        v.y = tile[4 * nq + 1][zl];
        v.z = tile[4 * nq + 2][zl];
        v.w = tile[4 * nq + 3][zl];
        __stcs((float4*)(op + (size_t)zl * NN + 4 * nq), v);
    }
}

// ---------------------------------------------------------------------------
// Check kernel: int8 SIMD min-sum, 4 z per thread packed in u32. Reads x2
// from permuted rows (funnel shift), writes prev to permuted rows via smem
// staging. CTAs with blockIdx.x >= MM/CM are fused out-writers streaming
// out[it-1] from g_t16 (read-only; overlaps check compute; no race).
// ---------------------------------------------------------------------------
__global__ void __launch_bounds__(CT * CM)
check_kernel(const int* __restrict__ shift,
             const float* __restrict__ cnw,
             float* __restrict__ out_prev,
             int it) {
    const int bxx = blockIdx.x;
    const int b   = blockIdx.y;
    const int tid = threadIdx.y * CT + threadIdx.x;

    if (bxx >= MM / CM) {                 // ---- fused out-writer CTA ----
        write_out_part(bxx - MM / CM, b, out_prev, tid);
        return;
    }

    const int m  = bxx * CM + threadIdx.y;
    const int t  = threadIdx.x;
    const int ty = threadIdx.y;

    __shared__ uint8_t  lutb[32];
    __shared__ uint32_t stage[CM][DC][CT];   // rotated message rows
    if (ty == 0 && t < 32) {
        const float w = cnw[it];
        lutb[t] = (uint8_t)(int)fminf(rintf(w * (float)t), 31.0f);
    }
    __syncthreads();

    const size_t bbase = (size_t)(b * EE) * ZZ;

    int b0[DC], ro[DC];
    uint32_t c[DC];
#pragma unroll
    for (int j = 0; j < DC; ++j) {
        const int e = m * DC + j;
        const int s = __ldg(shift + e);
        ro[j] = __ldg(g_edge_row + e);
        int byte0 = 4 * t + s;
        if (byte0 >= ZZ) byte0 -= ZZ;
        b0[j] = byte0;
        const int i0 = byte0 >> 2;
        int i1 = i0 + 1;
        if (i1 == ZZ / 4) i1 = 0;
        const uint32_t* p = (const uint32_t*)(g_x2 + bbase + ro[j]);
        c[j] = __funnelshift_r(p[i0], p[i1], (byte0 & 3) * 8);
    }

    uint32_t a[DC];
#pragma unroll
    for (int j = 0; j < DC; ++j) a[j] = __vabs4(c[j]);
    uint32_t m1 = a[0];
#pragma unroll
    for (int j = 1; j < DC; ++j) m1 = __vminu4(m1, a[j]);

    uint32_t eq[DC], cnt = 0, m2 = 0xFFFFFFFFu;
#pragma unroll
    for (int j = 0; j < DC; ++j) {
        eq[j] = __vcmpeq4(a[j], m1);
        cnt  += eq[j] & 0x01010101u;
        m2    = __vminu4(m2, a[j] | eq[j]);
    }
    const uint32_t unique = __vcmpeq4(cnt, 0x01010101u);
    m2 = __vminu4(m2, 0x1F1F1F1Fu);

    uint32_t tot = c[0];
#pragma unroll
    for (int j = 1; j < DC; ++j) tot ^= c[j];

    const uint32_t q1 =  (uint32_t)lutb[ m1        & 31]
                      | ((uint32_t)lutb[(m1 >> 8)  & 31] << 8)
                      | ((uint32_t)lutb[(m1 >> 16) & 31] << 16)
                      | ((uint32_t)lutb[(m1 >> 24) & 31] << 24);
    const uint32_t q2 =  (uint32_t)lutb[ m2        & 31]
                      | ((uint32_t)lutb[(m2 >> 8)  & 31] << 8)
                      | ((uint32_t)lutb[(m2 >> 16) & 31] << 16)
                      | ((uint32_t)lutb[(m2 >> 24) & 31] << 24);

#pragma unroll
    for (int j = 0; j < DC; ++j) {
        const uint32_t sel  = eq[j] & unique;
        const uint32_t q    = (q2 & sel) | (q1 & ~sel);
        const uint32_t nm   = __vcmpgts4(0u, tot ^ c[j]);
        const uint32_t outw = __vsub4(q ^ nm, nm);
        uint8_t* s8 = (uint8_t*)stage[ty][j];
#pragma unroll
        for (int k = 0; k < 4; ++k) {
            int bk = b0[j] + k;
            if (bk >= ZZ) bk -= ZZ;
            s8[bk] = (uint8_t)(outw >> (8 * k));
        }
    }
    __syncthreads();

#pragma unroll
    for (int j = 0; j < DC; ++j)
        *(uint32_t*)(g_prev + bbase + ro[j] + 4 * t) = stage[ty][j][t];
}

// ---------------------------------------------------------------------------
// Variable kernel: index-free, no smem, no sync. Block 128 = 32 z-u32 lanes
// x 4 n (one n per warp). Grid (3, 17, B). Contiguous prev rows -> 4-wide
// batched independent LDGs. Writes t16 (coalesced float4) and, if EMIT,
// the next x2 codes.
// ---------------------------------------------------------------------------
#define MK 0x00FF00FFu
template <bool EMIT>
__global__ void __launch_bounds__(128)
var_kernel(const float* __restrict__ xa) {
    const int b   = blockIdx.z;
    const int n   = blockIdx.y * 4 + (threadIdx.x >> 5);
    const int tx  = threadIdx.x & 31;
    const int zb  = 4 * (blockIdx.x * 32 + tx);

    // issue the (possibly DRAM) xa load FIRST so it overlaps the prev loads
    const float4 xv = __ldg((const float4*)(xa + (size_t)(b * NN + n) * ZZ + zb));

    const int d = g_var_deg[n];
    const int8_t* __restrict__ pb =
        g_prev + (size_t)(b * EE) * ZZ + g_var_start[n] + zb;

    uint32_t accE = 0, accO = 0;            // (byte ^ 0x80) sums in 16-bit lanes
    int i = 0;
    for (; i + 4 <= d; i += 4) {            // 4 independent loads per batch
        const uint32_t c0 = *(const uint32_t*)(pb + (i + 0) * ZZ) ^ 0x80808080u;
        const uint32_t c1 = *(const uint32_t*)(pb + (i + 1) * ZZ) ^ 0x80808080u;
        const uint32_t c2 = *(const uint32_t*)(pb + (i + 2) * ZZ) ^ 0x80808080u;
        const uint32_t c3 = *(const uint32_t*)(pb + (i + 3) * ZZ) ^ 0x80808080u;
        accE += (c0 & MK) + (c1 & MK) + (c2 & MK) + (c3 & MK);
        accO += ((c0 >> 8) & MK) + ((c1 >> 8) & MK)
              + ((c2 >> 8) & MK) + ((c3 >> 8) & MK);
    }
    for (; i < d; ++i) {
        const uint32_t c = *(const uint32_t*)(pb + i * ZZ) ^ 0x80808080u;
        accE += c & MK;
        accO += (c >> 8) & MK;
    }
    const int bias = d << 7;                // 128 * d per lane
    const float t0 = fmaf(xv.x, 16.0f, (float)((int)(accE & 0xFFFFu) - bias));
    const float t1 = fmaf(xv.y, 16.0f, (float)((int)(accO & 0xFFFFu) - bias));
    const float t2 = fmaf(xv.z, 16.0f, (float)((int)(accE >> 16)     - bias));
    const float t3 = fmaf(xv.w, 16.0f, (float)((int)(accO >> 16)     - bias));

    float4 tv; tv.x = t0; tv.y = t1; tv.z = t2; tv.w = t3;
    *(float4*)(g_t16 + (size_t)(b * NN + n) * ZZ + zb) = tv;

    if (EMIT) {
        int8_t* __restrict__ xb =
            g_x2 + (size_t)(b * EE) * ZZ + g_var_start[n] + zb;
        // pre-clamp so k fits int8; output-invariant (|t|>=63 -> code 31)
        const float tc0 = fminf(fmaxf(t0, -63.0f), 63.0f);
        const float tc1 = fminf(fmaxf(t1, -63.0f), 63.0f);
        const float tc2 = fminf(fmaxf(t2, -63.0f), 63.0f);
        const float tc3 = fminf(fmaxf(t3, -63.0f), 63.0f);
        for (int j = 0; j < d; ++j) {
            const uint32_t c = *(const uint32_t*)(pb + j * ZZ);   // L1 hit
            const int k0 = __float2int_rn(tc0 - (float)(int)(int8_t)(c));
            const int k1 = __float2int_rn(tc1 - (float)(int)(int8_t)(c >> 8));
            const int k2 = __float2int_rn(tc2 - (float)(int)(int8_t)(c >> 16));
            const int k3 = __float2int_rn(tc3 - (float)(int)(int8_t)(c >> 24));
            const uint32_t p1 = __byte_perm((uint32_t)k0, (uint32_t)k1, 0x0040);
            const uint32_t p2 = __byte_perm((uint32_t)k2, (uint32_t)k3, 0x0040);
            uint32_t pk = __byte_perm(p1, p2, 0x5410);
            pk = __vmins4(__vmaxs4(pk, 0xE1E1E1E1u), 0x1F1F1F1Fu);
            *(uint32_t*)(xb + j * ZZ) = pk;
        }
    }
}

// ---------------------------------------------------------------------------
// Standalone writer for the final iteration's output slice.
// ---------------------------------------------------------------------------
__global__ void __launch_bounds__(CT * CM)
out_writer(float* __restrict__ out_slice) {
    write_out_part(blockIdx.x, blockIdx.y,
                   out_slice, threadIdx.y * CT + threadIdx.x);
}

// ---------------------------------------------------------------------------
// Launch
// ---------------------------------------------------------------------------
extern "C" void kernel_launch(void* const* d_in, const int* in_sizes, int n_in,
                              void* d_out, int out_size) {
    const float* xa    = (const float*)d_in[0];   // (B, N, Z) f32
    const float* cnw   = (const float*)d_in[1];   // (ITERS,) f32
    const int*   etv   = (const int*)d_in[2];     // (E,) i32
    // d_in[3] = edge_to_check — grouping is implicit (repeat(arange(M), 7))
    const int*   shift = (const int*)d_in[4];     // (E,) i32
    float* out = (float*)d_out;                   // (ITERS, B, Z, N) f32

    setup_csr<<<1, EE>>>(etv);
    init_x2<<<dim3(EE, BB), CT>>>(xa, etv);

    const dim3 cblock(CT, CM);
    const dim3 vgrid(3, 17, BB);
    const size_t slice = (size_t)BB * ZZ * NN;

    for (int it = 0; it < NITER; ++it) {
        if (it == 0) {
            check_kernel<<<dim3(MM / CM, BB), cblock>>>(shift, cnw, nullptr, it);
        } else {
            check_kernel<<<dim3(MM / CM + WX, BB), cblock>>>(
                shift, cnw, out + (size_t)(it - 1) * slice, it);
        }
        if (it < NITER - 1)
            var_kernel<true><<<vgrid, 128>>>(xa);
        else
            var_kernel<false><<<vgrid, 128>>>(xa);
    }
    out_writer<<<dim3(WX, BB), cblock>>>(out + (size_t)(NITER - 1) * slice);
}